// round 2
// baseline (speedup 1.0000x reference)
#include <cuda_runtime.h>
#include <cstdint>

#define H_DIM 1024
#define K_TOT 2048
#define M_TOT 4096

// Transposed, tf32-rounded weights: Bt[g][h][k] = W_g[k][h]   (32 MB scratch)
static __device__ __align__(256) float g_Bt[4ull * H_DIM * K_TOT];

// ---------------------------------------------------------------------------
// Kernel 1: transpose + tf32-round the 4 gate weight matrices
// ---------------------------------------------------------------------------
__global__ void transpose_w_kernel(const float* __restrict__ Wf,
                                   const float* __restrict__ Wi,
                                   const float* __restrict__ Wg,
                                   const float* __restrict__ Wo) {
    __shared__ float tile[32][33];
    int g = blockIdx.z;
    const float* W = (g == 0) ? Wf : (g == 1) ? Wi : (g == 2) ? Wg : Wo;
    int k0 = blockIdx.x * 32, h0 = blockIdx.y * 32;
    int tx = threadIdx.x, ty = threadIdx.y;   // (32, 8)
#pragma unroll
    for (int i = 0; i < 32; i += 8)
        tile[ty + i][tx] = W[(size_t)(k0 + ty + i) * H_DIM + h0 + tx];
    __syncthreads();
#pragma unroll
    for (int i = 0; i < 32; i += 8) {
        float v = tile[tx][ty + i];
        uint32_t u;
        asm("cvt.rna.tf32.f32 %0, %1;" : "=r"(u) : "f"(v));
        g_Bt[((size_t)g * H_DIM + h0 + ty + i) * K_TOT + k0 + tx] = __uint_as_float(u);
    }
}

// ---------------------------------------------------------------------------
// Kernel 2: fused 4-gate GEMM + LSTM epilogue
//   Block tile: BM=128 rows (batch) x BH=32 h-columns x BK=32 k, 4 gates.
//   8 warps: 4 (m) x 2 (h). Warp tile 32 x 16 per gate.
// ---------------------------------------------------------------------------
#define BM 128
#define BH 32
#define BK 32
#define LDT 36   // smem row stride in floats (bank = 4r+c -> conflict-free)

__device__ __forceinline__ uint32_t f2tf(float f) {
    uint32_t u;
    asm("cvt.rna.tf32.f32 %0, %1;" : "=r"(u) : "f"(f));
    return u;
}

__device__ __forceinline__ void mma_tf32(float* c, const uint32_t* a, const uint32_t* b) {
    asm volatile(
        "mma.sync.aligned.m16n8k8.row.col.f32.tf32.tf32.f32 "
        "{%0,%1,%2,%3},{%4,%5,%6,%7},{%8,%9},{%0,%1,%2,%3};"
        : "+f"(c[0]), "+f"(c[1]), "+f"(c[2]), "+f"(c[3])
        : "r"(a[0]), "r"(a[1]), "r"(a[2]), "r"(a[3]), "r"(b[0]), "r"(b[1]));
}

__device__ __forceinline__ void cp16(uint32_t dst, const void* src) {
    asm volatile("cp.async.cg.shared.global [%0], [%1], 16;" ::"r"(dst), "l"(src));
}

__device__ __forceinline__ float sigf(float x) {
    return 1.0f / (1.0f + __expf(-x));
}

__global__ __launch_bounds__(256, 1) void lstm_gemm_kernel(
    const float* __restrict__ x, const float* __restrict__ h_prev,
    const float* __restrict__ c_prev,
    const float* __restrict__ bf, const float* __restrict__ bi,
    const float* __restrict__ bg, const float* __restrict__ bo,
    float* __restrict__ out) {

    extern __shared__ float smem[];
    float* As = smem;                        // [2][BM][LDT]
    float* Bs = smem + 2 * BM * LDT;         // [2][4][BH][LDT]

#define AS(s, r, c) As[((s) * BM + (r)) * LDT + (c)]
#define BS(s, g, r, c) Bs[(((s) * 4 + (g)) * BH + (r)) * LDT + (c)]

    const int h0 = blockIdx.x * BH;
    const int bm0 = blockIdx.y * BM;
    const int tid = threadIdx.x;
    const int lane = tid & 31;
    const int wid = tid >> 5;
    const int wm = wid & 3;    // m-warp: offset wm*32
    const int wn = wid >> 2;   // h-warp: offset wn*16

    // -------- async load of one k-stage --------
    const int lr = tid >> 3;          // 0..31
    const int lc = (tid & 7) * 4;     // float col offset (16B chunk)

    auto load_stage = [&](int kt, int s) {
        int k0 = kt * BK;
        const float* Ab = ((k0 < 1024) ? (x + k0) : (h_prev + (k0 - 1024)))
                          + (size_t)bm0 * 1024;
#pragma unroll
        for (int p = 0; p < 4; p++) {
            int row = lr + p * 32;
            cp16(__cvta_generic_to_shared(&AS(s, row, lc)),
                 Ab + (size_t)row * 1024 + lc);
            // gate p, rows h0+lr
            cp16(__cvta_generic_to_shared(&BS(s, p, lr, lc)),
                 g_Bt + ((size_t)(p * H_DIM + h0 + lr)) * K_TOT + k0 + lc);
        }
    };

    float acc[4][2][2][4];
#pragma unroll
    for (int g = 0; g < 4; g++)
#pragma unroll
        for (int mi = 0; mi < 2; mi++)
#pragma unroll
            for (int ni = 0; ni < 2; ni++)
#pragma unroll
                for (int e = 0; e < 4; e++) acc[g][mi][ni][e] = 0.0f;

    load_stage(0, 0);
    asm volatile("cp.async.commit_group;" ::: "memory");

    const int NKT = K_TOT / BK;  // 64
    for (int kt = 0; kt < NKT; kt++) {
        int s = kt & 1;
        if (kt < NKT - 1) {
            load_stage(kt + 1, s ^ 1);
            asm volatile("cp.async.commit_group;" ::: "memory");
            asm volatile("cp.async.wait_group 1;" ::: "memory");
        } else {
            asm volatile("cp.async.wait_group 0;" ::: "memory");
        }
        __syncthreads();

        const int ar = wm * 32 + (lane >> 2);
        const int nr = wn * 16 + (lane >> 2);
#pragma unroll
        for (int kk = 0; kk < BK; kk += 8) {
            const int c0 = kk + (lane & 3);
            uint32_t a[2][4];
#pragma unroll
            for (int mi = 0; mi < 2; mi++) {
                a[mi][0] = f2tf(AS(s, ar + mi * 16, c0));
                a[mi][1] = f2tf(AS(s, ar + mi * 16 + 8, c0));
                a[mi][2] = f2tf(AS(s, ar + mi * 16, c0 + 4));
                a[mi][3] = f2tf(AS(s, ar + mi * 16 + 8, c0 + 4));
            }
            uint32_t b[4][2][2];
#pragma unroll
            for (int g = 0; g < 4; g++)
#pragma unroll
                for (int ni = 0; ni < 2; ni++) {
                    b[g][ni][0] = __float_as_uint(BS(s, g, nr + ni * 8, c0));
                    b[g][ni][1] = __float_as_uint(BS(s, g, nr + ni * 8, c0 + 4));
                }
#pragma unroll
            for (int g = 0; g < 4; g++)
#pragma unroll
                for (int mi = 0; mi < 2; mi++)
#pragma unroll
                    for (int ni = 0; ni < 2; ni++)
                        mma_tf32(acc[g][mi][ni], a[mi], b[g][ni]);
        }
        __syncthreads();
    }

    // -------- fused LSTM epilogue --------
#pragma unroll
    for (int mi = 0; mi < 2; mi++)
#pragma unroll
        for (int ni = 0; ni < 2; ni++)
#pragma unroll
            for (int e = 0; e < 4; e++) {
                int m = bm0 + wm * 32 + mi * 16 + (lane >> 2) + ((e & 2) ? 8 : 0);
                int hh = h0 + wn * 16 + ni * 8 + (lane & 3) * 2 + (e & 1);
                float ft = sigf(acc[0][mi][ni][e] + bf[hh]);
                float it = sigf(acc[1][mi][ni][e] + bi[hh]);
                float gt = tanhf(acc[2][mi][ni][e] + bg[hh]);
                float ot = sigf(acc[3][mi][ni][e] + bo[hh]);
                float cp = c_prev[(size_t)m * H_DIM + hh];
                float cn = ft * cp + it * gt;
                float hn = ot * tanhf(cn);
                out[(size_t)m * H_DIM + hh] = hn;                          // h_next
                out[(size_t)M_TOT * H_DIM + (size_t)m * H_DIM + hh] = cn;  // c_next
            }
}

// ---------------------------------------------------------------------------
extern "C" void kernel_launch(void* const* d_in, const int* in_sizes, int n_in,
                              void* d_out, int out_size) {
    const float* x      = (const float*)d_in[0];
    const float* h_prev = (const float*)d_in[1];
    const float* c_prev = (const float*)d_in[2];
    const float* Wf = (const float*)d_in[3]; const float* bf = (const float*)d_in[4];
    const float* Wi = (const float*)d_in[5]; const float* bi = (const float*)d_in[6];
    const float* Wg = (const float*)d_in[7]; const float* bg = (const float*)d_in[8];
    const float* Wo = (const float*)d_in[9]; const float* bo = (const float*)d_in[10];
    float* out = (float*)d_out;

    transpose_w_kernel<<<dim3(K_TOT / 32, H_DIM / 32, 4), dim3(32, 8)>>>(Wf, Wi, Wg, Wo);

    const int smem_bytes = (2 * BM * LDT + 2 * 4 * BH * LDT) * (int)sizeof(float); // 73728
    cudaFuncSetAttribute(lstm_gemm_kernel,
                         cudaFuncAttributeMaxDynamicSharedMemorySize, smem_bytes);
    lstm_gemm_kernel<<<dim3(H_DIM / BH, M_TOT / BM), 256, smem_bytes>>>(
        x, h_prev, c_prev, bf, bi, bg, bo, out);
}

// round 4
// speedup vs baseline: 2.7444x; 2.7444x over previous
#include <cuda_runtime.h>
#include <cuda_fp16.h>
#include <cstdint>

#define H_DIM 1024
#define K_TOT 2048
#define M_TOT 4096
#define N_TOT 4096

#define BM 128
#define BN 256
#define BK 64                       // halves per k-stage
#define NSTAGE 3
#define A_STAGE_BYTES (BM * BK * 2)            // 16384
#define B_STAGE_BYTES (BN * BK * 2)            // 32768
#define STAGE_BYTES (A_STAGE_BYTES + B_STAGE_BYTES)   // 49152
#define SMEM_BYTES (NSTAGE * STAGE_BYTES)              // 147456

// fp16-staged operands
static __device__ __align__(256) __half g_Ah[(size_t)M_TOT * K_TOT];  // 16 MB
static __device__ __align__(256) __half g_Bh[(size_t)N_TOT * K_TOT];  // 16 MB

// ---------------------------------------------------------------------------
// helpers
// ---------------------------------------------------------------------------
__device__ __forceinline__ uint32_t smem_u32(const void* p) {
    uint32_t a;
    asm("{ .reg .u64 t; cvta.to.shared.u64 t, %1; cvt.u32.u64 %0, t; }" : "=r"(a) : "l"(p));
    return a;
}
__device__ __forceinline__ void cp16(uint32_t dst, const void* src) {
    asm volatile("cp.async.cg.shared.global [%0], [%1], 16;" ::"r"(dst), "l"(src));
}
__device__ __forceinline__ void ldsm4(uint32_t& r0, uint32_t& r1, uint32_t& r2, uint32_t& r3,
                                      uint32_t addr) {
    asm volatile("ldmatrix.sync.aligned.m8n8.x4.shared.b16 {%0,%1,%2,%3}, [%4];"
                 : "=r"(r0), "=r"(r1), "=r"(r2), "=r"(r3) : "r"(addr));
}
__device__ __forceinline__ void mma16816(float* c, const uint32_t* a, const uint32_t* b) {
    asm volatile(
        "mma.sync.aligned.m16n8k16.row.col.f32.f16.f16.f32 "
        "{%0,%1,%2,%3},{%4,%5,%6,%7},{%8,%9},{%0,%1,%2,%3};"
        : "+f"(c[0]), "+f"(c[1]), "+f"(c[2]), "+f"(c[3])
        : "r"(a[0]), "r"(a[1]), "r"(a[2]), "r"(a[3]), "r"(b[0]), "r"(b[1]));
}
__device__ __forceinline__ float sigf(float x) { return 1.0f / (1.0f + __expf(-x)); }

// ---------------------------------------------------------------------------
// Staging 1: W -> g_Bh[n][k] fp16, transposed, gate-interleaved:
//   n(h,g) = ((h>>3)<<5) | (g<<3) | (h&7)
// ---------------------------------------------------------------------------
__global__ void stage_w_kernel(const float* __restrict__ Wf, const float* __restrict__ Wi,
                               const float* __restrict__ Wg, const float* __restrict__ Wo) {
    __shared__ float tile[32][33];
    int g = blockIdx.z;
    const float* W = (g == 0) ? Wf : (g == 1) ? Wi : (g == 2) ? Wg : Wo;
    int k0 = blockIdx.x * 32, h0 = blockIdx.y * 32;
    int tx = threadIdx.x, ty = threadIdx.y;  // (32, 8)
#pragma unroll
    for (int i = 0; i < 32; i += 8)
        tile[ty + i][tx] = W[(size_t)(k0 + ty + i) * H_DIM + h0 + tx];
    __syncthreads();
#pragma unroll
    for (int i = 0; i < 32; i += 8) {
        int h = h0 + ty + i;
        int n = ((h >> 3) << 5) | (g << 3) | (h & 7);
        g_Bh[(size_t)n * K_TOT + k0 + tx] = __float2half_rn(tile[tx][ty + i]);
    }
}

// ---------------------------------------------------------------------------
// Staging 2: [x | h_prev] -> g_Ah[m][0..2047] fp16
// ---------------------------------------------------------------------------
__global__ void stage_a_kernel(const float* __restrict__ x, const float* __restrict__ h) {
    int idx = blockIdx.x * blockDim.x + threadIdx.x;  // 0 .. 4096*256-1
    int m = idx >> 8;
    int kq = (idx & 255) * 4;
    float4 vx = *(const float4*)&x[(size_t)m * 1024 + kq];
    float4 vh = *(const float4*)&h[(size_t)m * 1024 + kq];
    __half2 x01 = __floats2half2_rn(vx.x, vx.y), x23 = __floats2half2_rn(vx.z, vx.w);
    __half2 h01 = __floats2half2_rn(vh.x, vh.y), h23 = __floats2half2_rn(vh.z, vh.w);
    uint2 px, ph;
    px.x = *(uint32_t*)&x01; px.y = *(uint32_t*)&x23;
    ph.x = *(uint32_t*)&h01; ph.y = *(uint32_t*)&h23;
    *(uint2*)&g_Ah[(size_t)m * 2048 + kq] = px;
    *(uint2*)&g_Ah[(size_t)m * 2048 + 1024 + kq] = ph;
}

// ---------------------------------------------------------------------------
// Main: fp16 mma.sync GEMM (128x256 CTA tile, 64x64 warp tile) + LSTM epilogue
// 8 warps: wm = wid&1 (2 x 64 rows), wn = wid>>1 (4 x 64 n-cols)
// ---------------------------------------------------------------------------
__global__ __launch_bounds__(256, 1) void lstm_fp16_kernel(
    const float* __restrict__ c_prev,
    const float* __restrict__ bf, const float* __restrict__ bi,
    const float* __restrict__ bg, const float* __restrict__ bo,
    float* __restrict__ out) {

    extern __shared__ char smem[];
    const uint32_t sbase = smem_u32(smem);
    const int tid = threadIdx.x;
    const int lane = tid & 31;
    const int wid = tid >> 5;
    const int wm = wid & 1;
    const int wn = wid >> 1;

    const int bn0 = blockIdx.x * BN;
    const int bm0 = blockIdx.y * BM;

    // ---- per-lane ldmatrix address components (stage-invariant) ----
    const int q = lane >> 3;      // matrix index within x4
    const int lr = lane & 7;      // row within matrix
    uint32_t a_off[4], b_off[4];
    uint32_t a_rm[4], b_rm[4];
#pragma unroll
    for (int mt = 0; mt < 4; mt++) {
        int row = wm * 64 + mt * 16 + (q & 1) * 8 + lr;
        a_off[mt] = (uint32_t)row * 128;
        a_rm[mt] = (uint32_t)(row & 7);
    }
#pragma unroll
    for (int p = 0; p < 4; p++) {
        int row = wn * 64 + p * 16 + (q >> 1) * 8 + lr;
        b_off[p] = (uint32_t)row * 128;
        b_rm[p] = (uint32_t)(row & 7);
    }
    const uint32_t aqh = (uint32_t)(q >> 1);  // A chunk selector
    const uint32_t bql = (uint32_t)(q & 1);   // B chunk selector

    // ---- stage loader: 12 cp.async per thread ----
    auto load_stage = [&](int kt, int s) {
        const int k0 = kt * BK;
        const uint32_t ab = sbase + s * STAGE_BYTES;
        const uint32_t bb = ab + A_STAGE_BYTES;
        const __half* Asrc = g_Ah + (size_t)bm0 * K_TOT + k0;
        const __half* Bsrc = g_Bh + (size_t)bn0 * K_TOT + k0;
#pragma unroll
        for (int i = 0; i < 4; i++) {           // A: 1024 chunks
            int ch = i * 256 + tid;
            int r = ch >> 3, c = ch & 7;
            cp16(ab + (uint32_t)(r * 128 + ((c ^ (r & 7)) << 4)),
                 Asrc + (size_t)r * K_TOT + c * 8);
        }
#pragma unroll
        for (int i = 0; i < 8; i++) {           // B: 2048 chunks
            int ch = i * 256 + tid;
            int r = ch >> 3, c = ch & 7;
            cp16(bb + (uint32_t)(r * 128 + ((c ^ (r & 7)) << 4)),
                 Bsrc + (size_t)r * K_TOT + c * 8);
        }
    };

    float acc[4][8][4];
#pragma unroll
    for (int mt = 0; mt < 4; mt++)
#pragma unroll
        for (int j = 0; j < 8; j++)
#pragma unroll
            for (int e = 0; e < 4; e++) acc[mt][j][e] = 0.0f;

    load_stage(0, 0);
    asm volatile("cp.async.commit_group;" ::: "memory");
    load_stage(1, 1);
    asm volatile("cp.async.commit_group;" ::: "memory");

    const int NKT = K_TOT / BK;  // 32
    for (int kt = 0; kt < NKT; kt++) {
        const int s = kt % 3;
        __syncthreads();   // all warps done with stage (kt+2)%3 (consumed at kt-1)
        if (kt + 2 < NKT) {
            load_stage(kt + 2, (kt + 2) % 3);
            asm volatile("cp.async.commit_group;" ::: "memory");
            asm volatile("cp.async.wait_group 2;" ::: "memory");
        } else {
            asm volatile("cp.async.wait_group 0;" ::: "memory");
        }
        __syncthreads();   // stage kt visible to all

        const uint32_t As = sbase + s * STAGE_BYTES;
        const uint32_t Bs = As + A_STAGE_BYTES;
#pragma unroll
        for (int kk = 0; kk < 4; kk++) {
            uint32_t a[4][4], b[4][4];
#pragma unroll
            for (int mt = 0; mt < 4; mt++) {
                uint32_t c = (uint32_t)(kk * 2) + aqh;
                ldsm4(a[mt][0], a[mt][1], a[mt][2], a[mt][3],
                      As + a_off[mt] + ((c ^ a_rm[mt]) << 4));
            }
#pragma unroll
            for (int p = 0; p < 4; p++) {
                uint32_t c = (uint32_t)(kk * 2) + bql;
                ldsm4(b[p][0], b[p][1], b[p][2], b[p][3],
                      Bs + b_off[p] + ((c ^ b_rm[p]) << 4));
            }
#pragma unroll
            for (int mt = 0; mt < 4; mt++)
#pragma unroll
                for (int p = 0; p < 4; p++) {
                    mma16816(acc[mt][2 * p + 0], a[mt], &b[p][0]);
                    mma16816(acc[mt][2 * p + 1], a[mt], &b[p][2]);
                }
        }
    }

    // ---- fused LSTM epilogue (all in registers) ----
    const int l4 = lane >> 2, lq = lane & 3;
#pragma unroll
    for (int hblk = 0; hblk < 2; hblk++) {
        const int h = blockIdx.x * 64 + wn * 16 + hblk * 8 + lq * 2;
        const float2 Bf = *(const float2*)&bf[h];
        const float2 Bi = *(const float2*)&bi[h];
        const float2 Bg = *(const float2*)&bg[h];
        const float2 Bo = *(const float2*)&bo[h];
#pragma unroll
        for (int mt = 0; mt < 4; mt++) {
#pragma unroll
            for (int rb = 0; rb < 2; rb++) {
                const int m = bm0 + wm * 64 + mt * 16 + l4 + rb * 8;
                const float2 cp = *(const float2*)&c_prev[(size_t)m * H_DIM + h];
                float hn[2], cn[2];
#pragma unroll
                for (int ho = 0; ho < 2; ho++) {
                    const int e = rb * 2 + ho;
                    float ft = sigf(acc[mt][hblk * 4 + 0][e] + (ho ? Bf.y : Bf.x));
                    float it = sigf(acc[mt][hblk * 4 + 1][e] + (ho ? Bi.y : Bi.x));
                    float gt = tanhf(acc[mt][hblk * 4 + 2][e] + (ho ? Bg.y : Bg.x));
                    float ot = sigf(acc[mt][hblk * 4 + 3][e] + (ho ? Bo.y : Bo.x));
                    cn[ho] = ft * (ho ? cp.y : cp.x) + it * gt;
                    hn[ho] = ot * tanhf(cn[ho]);
                }
                *(float2*)&out[(size_t)m * H_DIM + h] = make_float2(hn[0], hn[1]);
                *(float2*)&out[(size_t)M_TOT * H_DIM + (size_t)m * H_DIM + h] =
                    make_float2(cn[0], cn[1]);
            }
        }
    }
}

// ---------------------------------------------------------------------------
extern "C" void kernel_launch(void* const* d_in, const int* in_sizes, int n_in,
                              void* d_out, int out_size) {
    const float* x      = (const float*)d_in[0];
    const float* h_prev = (const float*)d_in[1];
    const float* c_prev = (const float*)d_in[2];
    const float* Wf = (const float*)d_in[3]; const float* bf = (const float*)d_in[4];
    const float* Wi = (const float*)d_in[5]; const float* bi = (const float*)d_in[6];
    const float* Wg = (const float*)d_in[7]; const float* bg = (const float*)d_in[8];
    const float* Wo = (const float*)d_in[9]; const float* bo = (const float*)d_in[10];
    float* out = (float*)d_out;

    stage_w_kernel<<<dim3(K_TOT / 32, H_DIM / 32, 4), dim3(32, 8)>>>(Wf, Wi, Wg, Wo);
    stage_a_kernel<<<M_TOT * 256 / 256, 256>>>(x, h_prev);

    cudaFuncSetAttribute(lstm_fp16_kernel,
                         cudaFuncAttributeMaxDynamicSharedMemorySize, SMEM_BYTES);
    lstm_fp16_kernel<<<dim3(N_TOT / BN, M_TOT / BM), 256, SMEM_BYTES>>>(
        c_prev, bf, bi, bg, bo, out);
}

// round 5
// speedup vs baseline: 3.4938x; 1.2731x over previous
#include <cuda_runtime.h>
#include <cuda_fp16.h>
#include <cstdint>

#define H_DIM 1024
#define K_TOT 2048
#define M_TOT 4096
#define N_TOT 4096

#define BM 128
#define BN 128
#define BK 64                       // halves per k-stage
#define NSTAGE 3
#define A_STAGE_BYTES (BM * BK * 2)            // 16384
#define B_STAGE_BYTES (BN * BK * 2)            // 16384
#define STAGE_BYTES (A_STAGE_BYTES + B_STAGE_BYTES)   // 32768
#define SMEM_BYTES (NSTAGE * STAGE_BYTES)              // 98304

// fp16-staged operands
static __device__ __align__(256) __half g_Ah[(size_t)M_TOT * K_TOT];  // 16 MB
static __device__ __align__(256) __half g_Bh[(size_t)N_TOT * K_TOT];  // 16 MB

// ---------------------------------------------------------------------------
// helpers
// ---------------------------------------------------------------------------
__device__ __forceinline__ uint32_t smem_u32(const void* p) {
    uint32_t a;
    asm("{ .reg .u64 t; cvta.to.shared.u64 t, %1; cvt.u32.u64 %0, t; }" : "=r"(a) : "l"(p));
    return a;
}
__device__ __forceinline__ void cp16(uint32_t dst, const void* src) {
    asm volatile("cp.async.cg.shared.global [%0], [%1], 16;" ::"r"(dst), "l"(src));
}
__device__ __forceinline__ void ldsm4(uint32_t& r0, uint32_t& r1, uint32_t& r2, uint32_t& r3,
                                      uint32_t addr) {
    asm volatile("ldmatrix.sync.aligned.m8n8.x4.shared.b16 {%0,%1,%2,%3}, [%4];"
                 : "=r"(r0), "=r"(r1), "=r"(r2), "=r"(r3) : "r"(addr));
}
__device__ __forceinline__ void mma16816(float* c, const uint32_t* a, const uint32_t* b) {
    asm volatile(
        "mma.sync.aligned.m16n8k16.row.col.f32.f16.f16.f32 "
        "{%0,%1,%2,%3},{%4,%5,%6,%7},{%8,%9},{%0,%1,%2,%3};"
        : "+f"(c[0]), "+f"(c[1]), "+f"(c[2]), "+f"(c[3])
        : "r"(a[0]), "r"(a[1]), "r"(a[2]), "r"(a[3]), "r"(b[0]), "r"(b[1]));
}
__device__ __forceinline__ float sigf(float x) { return 1.0f / (1.0f + __expf(-x)); }

// ---------------------------------------------------------------------------
// Staging 1: W -> g_Bh[n][k] fp16, transposed, gate-interleaved:
//   n(h,g) = ((h>>3)<<5) | (g<<3) | (h&7)
// ---------------------------------------------------------------------------
__global__ void stage_w_kernel(const float* __restrict__ Wf, const float* __restrict__ Wi,
                               const float* __restrict__ Wg, const float* __restrict__ Wo) {
    __shared__ float tile[32][33];
    int g = blockIdx.z;
    const float* W = (g == 0) ? Wf : (g == 1) ? Wi : (g == 2) ? Wg : Wo;
    int k0 = blockIdx.x * 32, h0 = blockIdx.y * 32;
    int tx = threadIdx.x, ty = threadIdx.y;  // (32, 8)
#pragma unroll
    for (int i = 0; i < 32; i += 8)
        tile[ty + i][tx] = W[(size_t)(k0 + ty + i) * H_DIM + h0 + tx];
    __syncthreads();
#pragma unroll
    for (int i = 0; i < 32; i += 8) {
        int h = h0 + ty + i;
        int n = ((h >> 3) << 5) | (g << 3) | (h & 7);
        g_Bh[(size_t)n * K_TOT + k0 + tx] = __float2half_rn(tile[tx][ty + i]);
    }
}

// ---------------------------------------------------------------------------
// Staging 2: [x | h_prev] -> g_Ah[m][0..2047] fp16  (8 elems / thread, 16B stores)
// ---------------------------------------------------------------------------
__global__ void stage_a_kernel(const float* __restrict__ x, const float* __restrict__ h) {
    int idx = blockIdx.x * blockDim.x + threadIdx.x;  // 0 .. 4096*128-1
    int m = idx >> 7;
    int kq = (idx & 127) * 8;
    float4 vx0 = *(const float4*)&x[(size_t)m * 1024 + kq];
    float4 vx1 = *(const float4*)&x[(size_t)m * 1024 + kq + 4];
    float4 vh0 = *(const float4*)&h[(size_t)m * 1024 + kq];
    float4 vh1 = *(const float4*)&h[(size_t)m * 1024 + kq + 4];
    __half2 a0 = __floats2half2_rn(vx0.x, vx0.y), a1 = __floats2half2_rn(vx0.z, vx0.w);
    __half2 a2 = __floats2half2_rn(vx1.x, vx1.y), a3 = __floats2half2_rn(vx1.z, vx1.w);
    __half2 b0 = __floats2half2_rn(vh0.x, vh0.y), b1 = __floats2half2_rn(vh0.z, vh0.w);
    __half2 b2 = __floats2half2_rn(vh1.x, vh1.y), b3 = __floats2half2_rn(vh1.z, vh1.w);
    uint4 pa, pb;
    pa.x = *(uint32_t*)&a0; pa.y = *(uint32_t*)&a1; pa.z = *(uint32_t*)&a2; pa.w = *(uint32_t*)&a3;
    pb.x = *(uint32_t*)&b0; pb.y = *(uint32_t*)&b1; pb.z = *(uint32_t*)&b2; pb.w = *(uint32_t*)&b3;
    *(uint4*)&g_Ah[(size_t)m * 2048 + kq] = pa;
    *(uint4*)&g_Ah[(size_t)m * 2048 + 1024 + kq] = pb;
}

// ---------------------------------------------------------------------------
// Main: fp16 mma.sync GEMM (128x128 CTA tile, 64x32 warp tile) + LSTM epilogue
// 8 warps: wm = wid&1 (2 x 64 rows), wn = wid>>1 (4 x 32 n-cols). occ = 2.
// ---------------------------------------------------------------------------
__global__ __launch_bounds__(256, 2) void lstm_fp16_kernel(
    const float* __restrict__ c_prev,
    const float* __restrict__ bf, const float* __restrict__ bi,
    const float* __restrict__ bg, const float* __restrict__ bo,
    float* __restrict__ out) {

    extern __shared__ char smem[];
    const uint32_t sbase = smem_u32(smem);
    const int tid = threadIdx.x;
    const int lane = tid & 31;
    const int wid = tid >> 5;
    const int wm = wid & 1;
    const int wn = wid >> 1;

    const int bn0 = blockIdx.x * BN;
    const int bm0 = blockIdx.y * BM;

    // ---- per-lane ldmatrix address components (stage-invariant) ----
    const int q = lane >> 3;      // matrix index within x4
    const int lr = lane & 7;      // row within matrix
    uint32_t a_off[4], a_rm[4];
    uint32_t b_off[2], b_rm[2];
#pragma unroll
    for (int mt = 0; mt < 4; mt++) {
        int row = wm * 64 + mt * 16 + (q & 1) * 8 + lr;
        a_off[mt] = (uint32_t)row * 128;
        a_rm[mt] = (uint32_t)(row & 7);
    }
#pragma unroll
    for (int p = 0; p < 2; p++) {
        int row = wn * 32 + p * 16 + (q >> 1) * 8 + lr;
        b_off[p] = (uint32_t)row * 128;
        b_rm[p] = (uint32_t)(row & 7);
    }
    const uint32_t aqh = (uint32_t)(q >> 1);  // A chunk selector
    const uint32_t bql = (uint32_t)(q & 1);   // B chunk selector

    // ---- stage loader: 8 cp.async per thread ----
    auto load_stage = [&](int kt, int s) {
        const int k0 = kt * BK;
        const uint32_t ab = sbase + s * STAGE_BYTES;
        const uint32_t bb = ab + A_STAGE_BYTES;
        const __half* Asrc = g_Ah + (size_t)bm0 * K_TOT + k0;
        const __half* Bsrc = g_Bh + (size_t)bn0 * K_TOT + k0;
#pragma unroll
        for (int i = 0; i < 4; i++) {           // A + B: 1024 chunks each
            int ch = i * 256 + tid;
            int r = ch >> 3, c = ch & 7;
            uint32_t sw = (uint32_t)(r * 128 + ((c ^ (r & 7)) << 4));
            cp16(ab + sw, Asrc + (size_t)r * K_TOT + c * 8);
            cp16(bb + sw, Bsrc + (size_t)r * K_TOT + c * 8);
        }
    };

    float acc[4][4][4];   // [m-tile][gate(=n-8-block)][frag]
#pragma unroll
    for (int mt = 0; mt < 4; mt++)
#pragma unroll
        for (int j = 0; j < 4; j++)
#pragma unroll
            for (int e = 0; e < 4; e++) acc[mt][j][e] = 0.0f;

    load_stage(0, 0);
    asm volatile("cp.async.commit_group;" ::: "memory");
    load_stage(1, 1);
    asm volatile("cp.async.commit_group;" ::: "memory");

    const int NKT = K_TOT / BK;  // 32
    for (int kt = 0; kt < NKT; kt++) {
        const int s = kt % 3;
        if (kt < NKT - 1)
            asm volatile("cp.async.wait_group 1;" ::: "memory");  // stage kt ready
        else
            asm volatile("cp.async.wait_group 0;" ::: "memory");
        __syncthreads();  // stage kt visible; stage (kt+2)%3 free (consumed at kt-1)

        if (kt + 2 < NKT) {
            load_stage(kt + 2, (kt + 2) % 3);
            asm volatile("cp.async.commit_group;" ::: "memory");
        }

        const uint32_t As = sbase + s * STAGE_BYTES;
        const uint32_t Bs = As + A_STAGE_BYTES;
#pragma unroll
        for (int kk = 0; kk < 4; kk++) {
            uint32_t a[4][4], b[2][4];
            const uint32_t ca = (uint32_t)(kk * 2) + aqh;
            const uint32_t cb = (uint32_t)(kk * 2) + bql;
#pragma unroll
            for (int mt = 0; mt < 4; mt++)
                ldsm4(a[mt][0], a[mt][1], a[mt][2], a[mt][3],
                      As + a_off[mt] + ((ca ^ a_rm[mt]) << 4));
#pragma unroll
            for (int p = 0; p < 2; p++)
                ldsm4(b[p][0], b[p][1], b[p][2], b[p][3],
                      Bs + b_off[p] + ((cb ^ b_rm[p]) << 4));
#pragma unroll
            for (int mt = 0; mt < 4; mt++)
#pragma unroll
                for (int p = 0; p < 2; p++) {
                    mma16816(acc[mt][2 * p + 0], a[mt], &b[p][0]);
                    mma16816(acc[mt][2 * p + 1], a[mt], &b[p][2]);
                }
        }
    }

    // ---- fused LSTM epilogue (all in registers) ----
    // warp's 32 n-cols = 8 h values x 4 gates; j == gate, h = h_base + lq*2 + ho
    const int l4 = lane >> 2, lq = lane & 3;
    const int h = (bn0 >> 2) + wn * 8 + lq * 2;
    const float2 Bf = *(const float2*)&bf[h];
    const float2 Bi = *(const float2*)&bi[h];
    const float2 Bg = *(const float2*)&bg[h];
    const float2 Bo = *(const float2*)&bo[h];
#pragma unroll
    for (int mt = 0; mt < 4; mt++) {
#pragma unroll
        for (int rb = 0; rb < 2; rb++) {
            const int m = bm0 + wm * 64 + mt * 16 + l4 + rb * 8;
            const float2 cp = *(const float2*)&c_prev[(size_t)m * H_DIM + h];
            float hn[2], cn[2];
#pragma unroll
            for (int ho = 0; ho < 2; ho++) {
                const int e = rb * 2 + ho;
                float ft = sigf(acc[mt][0][e] + (ho ? Bf.y : Bf.x));
                float it = sigf(acc[mt][1][e] + (ho ? Bi.y : Bi.x));
                float gt = tanhf(acc[mt][2][e] + (ho ? Bg.y : Bg.x));
                float ot = sigf(acc[mt][3][e] + (ho ? Bo.y : Bo.x));
                cn[ho] = ft * (ho ? cp.y : cp.x) + it * gt;
                hn[ho] = ot * tanhf(cn[ho]);
            }
            *(float2*)&out[(size_t)m * H_DIM + h] = make_float2(hn[0], hn[1]);
            *(float2*)&out[(size_t)M_TOT * H_DIM + (size_t)m * H_DIM + h] =
                make_float2(cn[0], cn[1]);
        }
    }
}

// ---------------------------------------------------------------------------
extern "C" void kernel_launch(void* const* d_in, const int* in_sizes, int n_in,
                              void* d_out, int out_size) {
    const float* x      = (const float*)d_in[0];
    const float* h_prev = (const float*)d_in[1];
    const float* c_prev = (const float*)d_in[2];
    const float* Wf = (const float*)d_in[3]; const float* bf = (const float*)d_in[4];
    const float* Wi = (const float*)d_in[5]; const float* bi = (const float*)d_in[6];
    const float* Wg = (const float*)d_in[7]; const float* bg = (const float*)d_in[8];
    const float* Wo = (const float*)d_in[9]; const float* bo = (const float*)d_in[10];
    float* out = (float*)d_out;

    stage_w_kernel<<<dim3(K_TOT / 32, H_DIM / 32, 4), dim3(32, 8)>>>(Wf, Wi, Wg, Wo);
    stage_a_kernel<<<M_TOT * 128 / 256, 256>>>(x, h_prev);

    cudaFuncSetAttribute(lstm_fp16_kernel,
                         cudaFuncAttributeMaxDynamicSharedMemorySize, SMEM_BYTES);
    lstm_fp16_kernel<<<dim3(N_TOT / BN, M_TOT / BM), 256, SMEM_BYTES>>>(
        c_prev, bf, bi, bg, bo, out);
}